// round 5
// baseline (speedup 1.0000x reference)
#include <cuda_runtime.h>
#include <math.h>

#define N       1024
#define NN      (N * N)
#define NN4     (NN / 4)
#define RESTART 16
#define NV      17
#define K2C     0.3f
#define ACOEF   (4.0f + K2C)
#define EPSF    1e-12f
#define TPB     256
#define NBLK    1024             /* NBLK*TPB == NN4 exactly */
#define NCYC    4
#define NPART   18

// ---------------- device scratch (allocations forbidden) --------------------
__device__ float4 g_P[NV][NN4];   // unnormalized basis; P[16] never materialized
__device__ float4 g_zA[NN4];      // z' ping-pong
__device__ float4 g_zB[NN4];
__device__ float4 g_x[NN4];
__device__ float  g_part[NPART][NBLK];
__device__ float  g_sig[NV];          // sigma_k = 1/(||P[k]||+eps)
__device__ float  g_hp[NV];           // previous step raw dots <P[k], z'>
__device__ float  g_e[NV];            // combo coeffs for next P
__device__ float  g_ew;               // combo coeff on z'
__device__ float  g_Q[NV * NV];       // <P[k], P[m]>
__device__ float  g_Hm[NV * RESTART]; // zeros below subdiag persist
__device__ float  g_y[RESTART];       // y_k * sigma_k (pre-scaled)
__device__ float  g_beta;
__device__ unsigned g_cnt;

// ---------------- helpers ----------------------------------------------------
struct Off { int c, u, d, l, r; };

__device__ __forceinline__ Off mkoff(int idx) {
    Off o;
    int row = idx >> 8, c4 = idx & 255;
    o.c = idx;
    o.u = (((row - 1) & (N - 1)) << 8) | c4;
    o.d = (((row + 1) & (N - 1)) << 8) | c4;
    int rb = row << 10;
    o.l = rb | (((c4 << 2) - 1) & (N - 1));
    o.r = rb | (((c4 << 2) + 4) & (N - 1));
    return o;
}

__device__ __forceinline__ void loadCN(const float4* __restrict__ u4, const Off& o,
                                       float4& C, float4& NS) {
    C = u4[o.c];
    float4 U = u4[o.u], D = u4[o.d];
    const float* uf = (const float*)u4;
    float L = uf[o.l], R = uf[o.r];
    NS.x = L   + C.y + U.x + D.x;
    NS.y = C.x + C.z + U.y + D.y;
    NS.z = C.y + C.w + U.z + D.z;
    NS.w = C.z + R   + U.w + D.w;
}

__device__ __forceinline__ float dot4(float4 a, float4 b) {
    return a.x * b.x + a.y * b.y + a.z * b.z + a.w * b.w;
}

__device__ __forceinline__ float warpSum(float v) {
#pragma unroll
    for (int o = 16; o > 0; o >>= 1) v += __shfl_down_sync(0xffffffffu, v, o);
    return v;
}

// compile-time NK rows of per-block partials, then fence
template <int NK>
__device__ __forceinline__ void blockPartials(const float* acc) {
    __shared__ float sred[NK][TPB / 32];
    int lane = threadIdx.x & 31, warp = threadIdx.x >> 5;
#pragma unroll
    for (int k = 0; k < NK; k++) {
        float v = warpSum(acc[k]);
        if (lane == 0) sred[k][warp] = v;
    }
    __syncthreads();
    int t = threadIdx.x;
    if (t < NK) {
        float s = 0.f;
#pragma unroll
        for (int w = 0; w < TPB / 32; w++) s += sred[t][w];
        g_part[t][blockIdx.x] = s;
        __threadfence();
    }
    __syncthreads();
}

__device__ __forceinline__ bool isLastBlock() {
    __shared__ unsigned s_last;
    if (threadIdx.x == 0)
        s_last = (atomicAdd(&g_cnt, 1u) == (unsigned)(gridDim.x - 1));
    __syncthreads();
    return s_last != 0;
}

template <int NK>
__device__ __forceinline__ void finalTotals(float* s_tot) {
    int warp = threadIdx.x >> 5, lane = threadIdx.x & 31;
#pragma unroll
    for (int k = warp; k < NK; k += TPB / 32) {
        float s = 0.f;
        for (int b = lane; b < NBLK; b += 32) s += g_part[k][b];
        s = warpSum(s);
        if (lane == 0) s_tot[k] = s;
    }
    __syncthreads();
}

// ---------------- kernels ------------------------------------------------------
__global__ void __launch_bounds__(TPB) k_init(const float4* __restrict__ guess) {
    int i = blockIdx.x * TPB + threadIdx.x;
    g_x[i] = guess[i];
}

// P[0] = b - A(x)   (no reduction; beta computed by k_arn<0>)
__global__ void __launch_bounds__(TPB, 7) k_resid(const float4* __restrict__ b) {
    int i = blockIdx.x * TPB + threadIdx.x;
    Off o = mkoff(i);
    float4 c, n;
    loadCN(g_x, o, c, n);
    float4 bb = b[i];
    float4 r;
    r.x = bb.x - (ACOEF * c.x - n.x);
    r.y = bb.y - (ACOEF * c.y - n.y);
    r.z = bb.z - (ACOEF * c.z - n.z);
    r.w = bb.w - (ACOEF * c.w - n.w);
    g_P[0][i] = r;
}

// One Arnoldi step (compile-time J), single sweep:
//   p    = ew*zin - sum_{k<J} e_k P[k]        (5-point footprint each)
//   P[J] = p (J>0); zout = A(p)
//   reduce: h'_k = <P[k], zout> (k<J), h'_J = <p, zout>, nrm = <p,p>
// Epilogue: hn/sigma/Hm subdiag, Q column via scalar recurrence,
//   h2 = h - Gh, Hm[:,J] = h+h2, next combo coeffs e/ew.
template <int J>
__global__ void __launch_bounds__(TPB, 7) k_arn() {
    const float4* __restrict__ zin =
        (J == 0) ? g_P[0] : ((J & 1) ? g_zA : g_zB);
    float4* __restrict__ zout = (J & 1) ? g_zB : g_zA;

    __shared__ float es[RESTART];
    if (J > 0) {
        if (threadIdx.x < J) es[threadIdx.x] = g_e[threadIdx.x];
        __syncthreads();
    }
    float ew = (J == 0) ? 1.0f : g_ew;

    int i = blockIdx.x * TPB + threadIdx.x;
    Off o = mkoff(i);

    float4 pc, pn;
    {
        float4 C, NS;
        loadCN(zin, o, C, NS);
        pc.x = ew * C.x;  pc.y = ew * C.y;  pc.z = ew * C.z;  pc.w = ew * C.w;
        pn.x = ew * NS.x; pn.y = ew * NS.y; pn.z = ew * NS.z; pn.w = ew * NS.w;
    }
#pragma unroll
    for (int k = 0; k < J; k++) {
        float e = es[k];
        float4 C, NS;
        loadCN(g_P[k], o, C, NS);
        pc.x -= e * C.x;  pc.y -= e * C.y;  pc.z -= e * C.z;  pc.w -= e * C.w;
        pn.x -= e * NS.x; pn.y -= e * NS.y; pn.z -= e * NS.z; pn.w -= e * NS.w;
    }

    if (J > 0) g_P[J][i] = pc;

    float4 z;
    z.x = ACOEF * pc.x - pn.x;
    z.y = ACOEF * pc.y - pn.y;
    z.z = ACOEF * pc.z - pn.z;
    z.w = ACOEF * pc.w - pn.w;
    zout[i] = z;

    float acc[J + 2];
#pragma unroll
    for (int k = 0; k < J; k++)
        acc[k] = dot4(g_P[k][i], z);    // center reload: L1/L2 hit
    acc[J]     = dot4(pc, z);
    acc[J + 1] = dot4(pc, pc);

    blockPartials<J + 2>(acc);
    if (isLastBlock()) {
        __shared__ float tot[J + 2];
        finalTotals<J + 2>(tot);
        __shared__ float s_sig[NV], s_h[NV];
        int t = threadIdx.x;
        if (t == 0) {
            float hn = sqrtf(tot[J + 1]);
            g_sig[J] = 1.0f / (hn + EPSF);
            if (J > 0) g_Hm[J * RESTART + (J - 1)] = hn;
            else       g_beta = hn;
            g_Q[J * NV + J] = tot[J + 1];
        }
        __syncthreads();
        if (t <= J) s_sig[t] = g_sig[t];
        __syncthreads();
        // Q column J via recurrence: <P[t],P[J]> = ew*hp[t] - sum e_m Q[t][m]
        if (t < J) {
            float q = ew * g_hp[t];
#pragma unroll
            for (int m = 0; m < J; m++) q -= es[m] * g_Q[t * NV + m];
            g_Q[t * NV + J] = q;
            g_Q[J * NV + t] = q;
        }
        if (t <= J) {
            s_h[t]  = s_sig[t] * s_sig[J] * tot[t];   // true h_k
            g_hp[t] = tot[t];
        }
        __syncthreads();
        if (t <= J) {
            float gh = 0.f;
#pragma unroll
            for (int m = 0; m <= J; m++)
                gh += s_sig[t] * s_sig[m] * g_Q[t * NV + m] * s_h[m];
            float c = 2.0f * s_h[t] - gh;             // h + h2,  h2 = h - Gh
            g_Hm[t * RESTART + J] = c;
            g_e[t] = c * s_sig[t];
        }
        if (t == 0) { g_ew = s_sig[J]; g_cnt = 0; }
    }
}

// ||P[16]||^2 -> Hm[16][15]; then 16x16 normal-equations solve; y pre-scaled
__global__ void __launch_bounds__(TPB, 7) k_fin() {
    __shared__ float es[RESTART];
    if (threadIdx.x < RESTART) es[threadIdx.x] = g_e[threadIdx.x];
    __syncthreads();
    float ew = g_ew;

    int i = blockIdx.x * TPB + threadIdx.x;
    float4 zc = g_zB[i];   // z' of step 15 (odd -> wrote zB)
    float4 p;
    p.x = ew * zc.x; p.y = ew * zc.y; p.z = ew * zc.z; p.w = ew * zc.w;
#pragma unroll
    for (int k = 0; k < RESTART; k++) {
        float e = es[k];
        float4 v = g_P[k][i];
        p.x -= e * v.x; p.y -= e * v.y; p.z -= e * v.z; p.w -= e * v.w;
    }
    float acc[1];
    acc[0] = dot4(p, p);

    blockPartials<1>(acc);
    if (isLastBlock()) {
        __shared__ float tot[1];
        finalTotals<1>(tot);
        int t = threadIdx.x;
        if (t == 0) g_Hm[16 * RESTART + 15] = sqrtf(tot[0]);
        __syncthreads();

        __shared__ float sG[RESTART][RESTART], sf[RESTART], rhs[RESTART];
        {
            int a = t >> 4, b = t & 15;      // 256 threads = 16x16
            float su = 0.f;
            for (int r = 0; r < NV; r++)
                su += g_Hm[r * RESTART + a] * g_Hm[r * RESTART + b];
            sG[a][b] = su + ((a == b) ? EPSF : 0.f);
        }
        if (t < RESTART) rhs[t] = g_Hm[t] * g_beta;   // Hm row 0
        __syncthreads();

        for (int p2 = 0; p2 < RESTART; p2++) {
            if (t > p2 && t < RESTART) sf[t] = sG[t][p2] / sG[p2][p2];
            __syncthreads();
            int r = t >> 4, c = t & 15;
            if (r > p2 && c > p2) sG[r][c] -= sf[r] * sG[p2][c];
            if (t > p2 && t < RESTART) rhs[t] -= sf[t] * rhs[p2];
            __syncthreads();
        }
        if (t == 0) {
            for (int p2 = RESTART - 1; p2 >= 0; p2--) {
                float su = rhs[p2];
                for (int c = p2 + 1; c < RESTART; c++) su -= sG[p2][c] * rhs[c];
                rhs[p2] = su / sG[p2][p2];
            }
        }
        __syncthreads();
        if (t < RESTART) g_y[t] = rhs[t] * g_sig[t];
        if (t == 0) g_cnt = 0;
    }
}

// x += sum_k y_k P[k]  (y pre-scaled by sigma); optionally emit
__global__ void __launch_bounds__(TPB, 7) k_xupd(float4* __restrict__ out) {
    __shared__ float ys[RESTART];
    if (threadIdx.x < RESTART) ys[threadIdx.x] = g_y[threadIdx.x];
    __syncthreads();
    int i = blockIdx.x * TPB + threadIdx.x;
    float4 s = g_x[i];
#pragma unroll
    for (int k = 0; k < RESTART; k++) {
        float y = ys[k];
        float4 v = g_P[k][i];
        s.x += y * v.x; s.y += y * v.y; s.z += y * v.z; s.w += y * v.w;
    }
    g_x[i] = s;
    if (out) out[i] = s;
}

// ---------------- host orchestration ----------------------------------------
static void launch_arn(int j) {
    switch (j) {
        case 0:  k_arn<0><<<NBLK, TPB>>>();  break;
        case 1:  k_arn<1><<<NBLK, TPB>>>();  break;
        case 2:  k_arn<2><<<NBLK, TPB>>>();  break;
        case 3:  k_arn<3><<<NBLK, TPB>>>();  break;
        case 4:  k_arn<4><<<NBLK, TPB>>>();  break;
        case 5:  k_arn<5><<<NBLK, TPB>>>();  break;
        case 6:  k_arn<6><<<NBLK, TPB>>>();  break;
        case 7:  k_arn<7><<<NBLK, TPB>>>();  break;
        case 8:  k_arn<8><<<NBLK, TPB>>>();  break;
        case 9:  k_arn<9><<<NBLK, TPB>>>();  break;
        case 10: k_arn<10><<<NBLK, TPB>>>(); break;
        case 11: k_arn<11><<<NBLK, TPB>>>(); break;
        case 12: k_arn<12><<<NBLK, TPB>>>(); break;
        case 13: k_arn<13><<<NBLK, TPB>>>(); break;
        case 14: k_arn<14><<<NBLK, TPB>>>(); break;
        case 15: k_arn<15><<<NBLK, TPB>>>(); break;
    }
}

extern "C" void kernel_launch(void* const* d_in, const int* in_sizes, int n_in,
                              void* d_out, int out_size) {
    (void)in_sizes; (void)n_in; (void)out_size;
    const float4* src   = (const float4*)d_in[0];
    const float4* guess = (const float4*)d_in[1];
    float4* out = (float4*)d_out;

    k_init<<<NBLK, TPB>>>(guess);

    for (int c = 0; c < NCYC; c++) {
        k_resid<<<NBLK, TPB>>>(src);
        for (int j = 0; j < RESTART; j++)
            launch_arn(j);
        k_fin<<<NBLK, TPB>>>();
        k_xupd<<<NBLK, TPB>>>(c == NCYC - 1 ? out : nullptr);
    }
}

// round 6
// speedup vs baseline: 2.8184x; 2.8184x over previous
#include <cuda_runtime.h>
#include <math.h>

#define N       1024
#define NN      (N * N)
#define NN4     (NN / 4)
#define RESTART 16
#define NV      17
#define K2C     0.3f
#define ACOEF   (4.0f + K2C)
#define EPSF    1e-12f
#define TPB     256
#define NBLK    1024             /* NBLK*TPB == NN4 exactly */
#define NCYC    4
#define NPART   18

// ---------------- device scratch (allocations forbidden) --------------------
__device__ float4 g_P[NV][NN4];   // unnormalized basis; P[16] never materialized
__device__ float4 g_zA[NN4];      // z' ping-pong
__device__ float4 g_zB[NN4];
__device__ float4 g_x[NN4];
__device__ float  g_part[NPART][NBLK];
__device__ float  g_sig[NV];          // sigma_k = 1/(||P[k]||+eps)
__device__ float  g_hp[NV];           // previous step raw dots <P[k], z'>
__device__ float  g_e[NV];            // combo coeffs for next P
__device__ float  g_ew;               // combo coeff on z'
__device__ float  g_Q[NV * NV];       // <P[k], P[m]>
__device__ float  g_Hm[NV * RESTART]; // zeros below subdiag persist
__device__ float  g_y[RESTART];       // y_k * sigma_k (pre-scaled)
__device__ float  g_beta;
__device__ unsigned g_cnt;

// ---------------- helpers ----------------------------------------------------
struct Off { int c, u, d, l, r; };

__device__ __forceinline__ Off mkoff(int idx) {
    Off o;
    int row = idx >> 8, c4 = idx & 255;
    o.c = idx;
    o.u = (((row - 1) & (N - 1)) << 8) | c4;
    o.d = (((row + 1) & (N - 1)) << 8) | c4;
    int rb = row << 10;
    o.l = rb | (((c4 << 2) - 1) & (N - 1));
    o.r = rb | (((c4 << 2) + 4) & (N - 1));
    return o;
}

// footprint load: center + neighbor-sum; L/R scalars via warp shuffle
// (warps are 32-contiguous in i and rows are 256-f4-aligned, so c4==0 / c4==255
//  only ever occur at lane 0 / lane 31)
__device__ __forceinline__ void loadF(const float4* __restrict__ u4, const Off& o,
                                      int lane, float4& C, float4& NS) {
    C = u4[o.c];
    float4 U = u4[o.u], D = u4[o.d];
    float L = __shfl_up_sync(0xffffffffu, C.w, 1);
    float R = __shfl_down_sync(0xffffffffu, C.x, 1);
    if (lane == 0)  L = ((const float*)u4)[o.l];
    if (lane == 31) R = ((const float*)u4)[o.r];
    NS.x = L   + C.y + U.x + D.x;
    NS.y = C.x + C.z + U.y + D.y;
    NS.z = C.y + C.w + U.z + D.z;
    NS.w = C.z + R   + U.w + D.w;
}

__device__ __forceinline__ float dot4(float4 a, float4 b) {
    return a.x * b.x + a.y * b.y + a.z * b.z + a.w * b.w;
}

__device__ __forceinline__ float warpSum(float v) {
#pragma unroll
    for (int o = 16; o > 0; o >>= 1) v += __shfl_down_sync(0xffffffffu, v, o);
    return v;
}

__device__ __forceinline__ bool isLastBlock() {
    __shared__ unsigned s_last;
    if (threadIdx.x == 0)
        s_last = (atomicAdd(&g_cnt, 1u) == (unsigned)(gridDim.x - 1));
    __syncthreads();
    return s_last != 0;
}

// ---------------- kernels ------------------------------------------------------
__global__ void __launch_bounds__(TPB) k_init(const float4* __restrict__ guess) {
    int i = blockIdx.x * TPB + threadIdx.x;
    g_x[i] = guess[i];
}

// P[0] = b - A(x)   (beta computed by k_arn(0))
__global__ void __launch_bounds__(TPB, 6) k_resid(const float4* __restrict__ b) {
    int i = blockIdx.x * TPB + threadIdx.x;
    int lane = threadIdx.x & 31;
    Off o = mkoff(i);
    float4 c, n;
    loadF(g_x, o, lane, c, n);
    float4 bb = b[i];
    float4 r;
    r.x = bb.x - (ACOEF * c.x - n.x);
    r.y = bb.y - (ACOEF * c.y - n.y);
    r.z = bb.z - (ACOEF * c.z - n.z);
    r.w = bb.w - (ACOEF * c.w - n.w);
    g_P[0][i] = r;
}

// One Arnoldi step (runtime j), single sweep, per-iteration reductions:
//   p    = ew*zin - sum_{k<j} e_k P[k]   (3 LDG.128 + 2 SHFL footprint each)
//   P[j] = p (j>0); zout = A(p)
//   dots <P[k],z> reduced per-k into shared; plus <p,z>, <p,p>
// Epilogue: Gram recurrence -> Hm column, next combo coeffs (validated R4 math)
__global__ void __launch_bounds__(TPB, 6) k_arn(int j) {
    const float4* __restrict__ zin;
    float4* __restrict__ zout;
    if (j == 0)      { zin = g_P[0]; zout = g_zA; }
    else if (j & 1)  { zin = g_zA;   zout = g_zB; }
    else             { zin = g_zB;   zout = g_zA; }

    __shared__ float es[RESTART];
    if (threadIdx.x < RESTART) es[threadIdx.x] = g_e[threadIdx.x];
    __syncthreads();
    float ew = (j == 0) ? 1.0f : g_ew;

    int i = blockIdx.x * TPB + threadIdx.x;
    int lane = threadIdx.x & 31, warp = threadIdx.x >> 5;
    Off o = mkoff(i);

    // ---- pass 1: linear combination with 5-point footprints ----
    float4 pc, pn;
    {
        float4 C, NS;
        loadF(zin, o, lane, C, NS);
        pc.x = ew * C.x;  pc.y = ew * C.y;  pc.z = ew * C.z;  pc.w = ew * C.w;
        pn.x = ew * NS.x; pn.y = ew * NS.y; pn.z = ew * NS.z; pn.w = ew * NS.w;
    }
#pragma unroll 2
    for (int k = 0; k < j; k++) {
        float e = es[k];
        float4 C, NS;
        loadF(g_P[k], o, lane, C, NS);
        pc.x -= e * C.x;  pc.y -= e * C.y;  pc.z -= e * C.z;  pc.w -= e * C.w;
        pn.x -= e * NS.x; pn.y -= e * NS.y; pn.z -= e * NS.z; pn.w -= e * NS.w;
    }

    if (j > 0) g_P[j][i] = pc;

    float4 z;
    z.x = ACOEF * pc.x - pn.x;
    z.y = ACOEF * pc.y - pn.y;
    z.z = ACOEF * pc.z - pn.z;
    z.w = ACOEF * pc.w - pn.w;
    zout[i] = z;

    // ---- pass 2: dots, reduced per iteration (no register arrays) ----
    __shared__ float sred[NPART][TPB / 32];
#pragma unroll 4
    for (int k = 0; k < j; k++) {
        float d = warpSum(dot4(g_P[k][i], z));
        if (lane == 0) sred[k][warp] = d;
    }
    {
        float dj = warpSum(dot4(pc, z));
        if (lane == 0) sred[j][warp] = dj;
        float nr = warpSum(dot4(pc, pc));
        if (lane == 0) sred[j + 1][warp] = nr;
    }
    __syncthreads();
    int t = threadIdx.x;
    int nk = j + 2;
    if (t < nk) {
        float s = 0.f;
#pragma unroll
        for (int w = 0; w < TPB / 32; w++) s += sred[t][w];
        g_part[t][blockIdx.x] = s;
        __threadfence();
    }
    __syncthreads();

    if (isLastBlock()) {
        __shared__ float tot[NPART];
        for (int k = warp; k < nk; k += TPB / 32) {
            float s = 0.f;
            for (int b = lane; b < NBLK; b += 32) s += g_part[k][b];
            s = warpSum(s);
            if (lane == 0) tot[k] = s;
        }
        __syncthreads();

        __shared__ float s_sig[NV], s_h[NV];
        if (t == 0) {
            float hn = sqrtf(tot[j + 1]);
            g_sig[j] = 1.0f / (hn + EPSF);
            if (j > 0) g_Hm[j * RESTART + (j - 1)] = hn;
            else       g_beta = hn;
            g_Q[j * NV + j] = tot[j + 1];
        }
        __syncthreads();
        if (t <= j) s_sig[t] = g_sig[t];
        __syncthreads();
        // Q column j via recurrence: <P[t],P[j]> = ew*hp[t] - sum_m e_m Q[t][m]
        if (t < j) {
            float q = ew * g_hp[t];
            for (int m = 0; m < j; m++) q -= es[m] * g_Q[t * NV + m];
            g_Q[t * NV + j] = q;
            g_Q[j * NV + t] = q;
        }
        if (t <= j) {
            s_h[t]  = s_sig[t] * s_sig[j] * tot[t];   // true h_k
            g_hp[t] = tot[t];
        }
        __syncthreads();
        if (t <= j) {
            float gh = 0.f;
            for (int m = 0; m <= j; m++)
                gh += s_sig[t] * s_sig[m] * g_Q[t * NV + m] * s_h[m];
            float c = 2.0f * s_h[t] - gh;             // h + h2,  h2 = h - Gh
            g_Hm[t * RESTART + j] = c;
            g_e[t] = c * s_sig[t];
        }
        if (t == 0) { g_ew = s_sig[j]; g_cnt = 0; }
    }
}

// ||P[16]||^2 -> Hm[16][15]; then 16x16 normal-equations solve; y pre-scaled
__global__ void __launch_bounds__(TPB, 6) k_fin() {
    __shared__ float es[RESTART];
    if (threadIdx.x < RESTART) es[threadIdx.x] = g_e[threadIdx.x];
    __syncthreads();
    float ew = g_ew;

    int i = blockIdx.x * TPB + threadIdx.x;
    int lane = threadIdx.x & 31, warp = threadIdx.x >> 5;
    float4 zc = g_zB[i];   // z' of step 15 (odd -> wrote zB)
    float4 p;
    p.x = ew * zc.x; p.y = ew * zc.y; p.z = ew * zc.z; p.w = ew * zc.w;
#pragma unroll 4
    for (int k = 0; k < RESTART; k++) {
        float e = es[k];
        float4 v = g_P[k][i];
        p.x -= e * v.x; p.y -= e * v.y; p.z -= e * v.z; p.w -= e * v.w;
    }
    __shared__ float sred[TPB / 32];
    float nr = warpSum(dot4(p, p));
    if (lane == 0) sred[warp] = nr;
    __syncthreads();
    if (threadIdx.x == 0) {
        float s = 0.f;
#pragma unroll
        for (int w = 0; w < TPB / 32; w++) s += sred[w];
        g_part[0][blockIdx.x] = s;
        __threadfence();
    }
    __syncthreads();

    if (isLastBlock()) {
        int t = threadIdx.x;
        __shared__ float tot[1];
        if (warp == 0) {
            float s = 0.f;
            for (int b = lane; b < NBLK; b += 32) s += g_part[0][b];
            s = warpSum(s);
            if (lane == 0) tot[0] = s;
        }
        __syncthreads();
        if (t == 0) g_Hm[16 * RESTART + 15] = sqrtf(tot[0]);
        __syncthreads();

        __shared__ float sG[RESTART][RESTART], sf[RESTART], rhs[RESTART];
        {
            int a = t >> 4, b = t & 15;      // 256 threads = 16x16
            float su = 0.f;
            for (int r = 0; r < NV; r++)
                su += g_Hm[r * RESTART + a] * g_Hm[r * RESTART + b];
            sG[a][b] = su + ((a == b) ? EPSF : 0.f);
        }
        if (t < RESTART) rhs[t] = g_Hm[t] * g_beta;   // Hm row 0
        __syncthreads();

        for (int p2 = 0; p2 < RESTART; p2++) {
            if (t > p2 && t < RESTART) sf[t] = sG[t][p2] / sG[p2][p2];
            __syncthreads();
            int r = t >> 4, c = t & 15;
            if (r > p2 && c > p2) sG[r][c] -= sf[r] * sG[p2][c];
            if (t > p2 && t < RESTART) rhs[t] -= sf[t] * rhs[p2];
            __syncthreads();
        }
        if (t == 0) {
            for (int p2 = RESTART - 1; p2 >= 0; p2--) {
                float su = rhs[p2];
                for (int c = p2 + 1; c < RESTART; c++) su -= sG[p2][c] * rhs[c];
                rhs[p2] = su / sG[p2][p2];
            }
        }
        __syncthreads();
        if (t < RESTART) g_y[t] = rhs[t] * g_sig[t];
        if (t == 0) g_cnt = 0;
    }
}

// x += sum_k y_k P[k]  (y pre-scaled by sigma); optionally emit
__global__ void __launch_bounds__(TPB, 6) k_xupd(float4* __restrict__ out) {
    __shared__ float ys[RESTART];
    if (threadIdx.x < RESTART) ys[threadIdx.x] = g_y[threadIdx.x];
    __syncthreads();
    int i = blockIdx.x * TPB + threadIdx.x;
    float4 s = g_x[i];
#pragma unroll 4
    for (int k = 0; k < RESTART; k++) {
        float y = ys[k];
        float4 v = g_P[k][i];
        s.x += y * v.x; s.y += y * v.y; s.z += y * v.z; s.w += y * v.w;
    }
    g_x[i] = s;
    if (out) out[i] = s;
}

// ---------------- host orchestration ----------------------------------------
extern "C" void kernel_launch(void* const* d_in, const int* in_sizes, int n_in,
                              void* d_out, int out_size) {
    (void)in_sizes; (void)n_in; (void)out_size;
    const float4* src   = (const float4*)d_in[0];
    const float4* guess = (const float4*)d_in[1];
    float4* out = (float4*)d_out;

    k_init<<<NBLK, TPB>>>(guess);

    for (int c = 0; c < NCYC; c++) {
        k_resid<<<NBLK, TPB>>>(src);
        for (int j = 0; j < RESTART; j++)
            k_arn<<<NBLK, TPB>>>(j);
        k_fin<<<NBLK, TPB>>>();
        k_xupd<<<NBLK, TPB>>>(c == NCYC - 1 ? out : nullptr);
    }
}

// round 7
// speedup vs baseline: 3.7902x; 1.3448x over previous
#include <cuda_runtime.h>
#include <math.h>

#define N       1024
#define NN      (N * N)
#define NN4     (NN / 4)
#define RESTART 16
#define NV      17
#define K2C     0.3f
#define ACOEF   (4.0f + K2C)
#define EPSF    1e-12f
#define TPB     256
#define NBLK    512              /* 512 blocks x 256 threads x 2 points = NN4 */
#define NCYC    4
#define NPART   18

// ---------------- device scratch (allocations forbidden) --------------------
__device__ float4 g_P[NV][NN4];   // unnormalized basis; P[16] never materialized
__device__ float4 g_zA[NN4];      // z' ping-pong
__device__ float4 g_zB[NN4];
__device__ float4 g_x[NN4];
__device__ float  g_part[NPART][NBLK];
__device__ float  g_sig[NV];          // sigma_k = 1/(||P[k]||+eps)
__device__ float  g_hp[NV];           // previous step raw dots <P[k], z'>
__device__ float  g_e[NV];            // combo coeffs for next P
__device__ float  g_ew;               // combo coeff on z'
__device__ float  g_Q[NV * NV];       // <P[k], P[m]>
__device__ float  g_Hm[NV * RESTART]; // zeros below subdiag persist
__device__ float  g_y[RESTART];       // y_k * sigma_k (pre-scaled)
__device__ float  g_beta;
__device__ unsigned g_cnt;

// ---------------- helpers ----------------------------------------------------
// per-thread geometry: two vertically adjacent points (rows 2q, 2q+1), col c
struct Geo {
    int i1, i2;      // f4 indices of the two centers
    int up, dn;      // f4 indices of row 2q-1, row 2q+2 (periodic)
    int l1, r1;      // scalar indices for row 2q wrap L/R
    int l2, r2;      // scalar indices for row 2q+1 wrap L/R
};

__device__ __forceinline__ Geo mkgeo() {
    int g   = blockIdx.x * TPB + threadIdx.x;
    int q   = g >> 8;            // row pair 0..511
    int col = g & 255;           // f4 column
    int r1  = q << 1, r2 = r1 + 1;
    Geo o;
    o.i1 = (r1 << 8) | col;
    o.i2 = (r2 << 8) | col;
    o.up = (((r1 - 1) & (N - 1)) << 8) | col;
    o.dn = (((r2 + 1) & (N - 1)) << 8) | col;
    int cl = ((col << 2) - 1) & (N - 1);
    int cr = ((col << 2) + 4) & (N - 1);
    o.l1 = (r1 << 10) | cl;  o.r1 = (r1 << 10) | cr;
    o.l2 = (r2 << 10) | cl;  o.r2 = (r2 << 10) | cr;
    return o;
}

// footprint for both points: 4 LDG.128 (C1,C2,U,D); L/R via warp shuffle,
// edge lanes (0/31) patch from memory (col 0/255 wrap).
__device__ __forceinline__ void loadF2(const float4* __restrict__ u4, const Geo& o,
                                       int lane,
                                       float4& C1, float4& NS1,
                                       float4& C2, float4& NS2) {
    C1 = u4[o.i1];
    C2 = u4[o.i2];
    float4 U = u4[o.up], D = u4[o.dn];
    float L1 = __shfl_up_sync(0xffffffffu, C1.w, 1);
    float R1 = __shfl_down_sync(0xffffffffu, C1.x, 1);
    float L2 = __shfl_up_sync(0xffffffffu, C2.w, 1);
    float R2 = __shfl_down_sync(0xffffffffu, C2.x, 1);
    if (lane == 0)  { L1 = ((const float*)u4)[o.l1]; L2 = ((const float*)u4)[o.l2]; }
    if (lane == 31) { R1 = ((const float*)u4)[o.r1]; R2 = ((const float*)u4)[o.r2]; }
    // row 2q: up = U, down = C2 ; row 2q+1: up = C1, down = D
    NS1.x = L1   + C1.y + U.x  + C2.x;
    NS1.y = C1.x + C1.z + U.y  + C2.y;
    NS1.z = C1.y + C1.w + U.z  + C2.z;
    NS1.w = C1.z + R1   + U.w  + C2.w;
    NS2.x = L2   + C2.y + C1.x + D.x;
    NS2.y = C2.x + C2.z + C1.y + D.y;
    NS2.z = C2.y + C2.w + C1.z + D.z;
    NS2.w = C2.z + R2   + C1.w + D.w;
}

__device__ __forceinline__ float dot4(float4 a, float4 b) {
    return a.x * b.x + a.y * b.y + a.z * b.z + a.w * b.w;
}

__device__ __forceinline__ float warpSum(float v) {
#pragma unroll
    for (int o = 16; o > 0; o >>= 1) v += __shfl_down_sync(0xffffffffu, v, o);
    return v;
}

__device__ __forceinline__ bool isLastBlock() {
    __shared__ unsigned s_last;
    if (threadIdx.x == 0)
        s_last = (atomicAdd(&g_cnt, 1u) == (unsigned)(gridDim.x - 1));
    __syncthreads();
    return s_last != 0;
}

// ---------------- kernels ------------------------------------------------------
__global__ void __launch_bounds__(TPB) k_init(const float4* __restrict__ guess) {
    Geo o = mkgeo();
    g_x[o.i1] = guess[o.i1];
    g_x[o.i2] = guess[o.i2];
}

// P[0] = b - A(x)   (beta computed by k_arn(0))
__global__ void __launch_bounds__(TPB, 4) k_resid(const float4* __restrict__ b) {
    Geo o = mkgeo();
    int lane = threadIdx.x & 31;
    float4 C1, NS1, C2, NS2;
    loadF2(g_x, o, lane, C1, NS1, C2, NS2);
    float4 b1 = b[o.i1], b2 = b[o.i2], r;
    r.x = b1.x - (ACOEF * C1.x - NS1.x);
    r.y = b1.y - (ACOEF * C1.y - NS1.y);
    r.z = b1.z - (ACOEF * C1.z - NS1.z);
    r.w = b1.w - (ACOEF * C1.w - NS1.w);
    g_P[0][o.i1] = r;
    r.x = b2.x - (ACOEF * C2.x - NS2.x);
    r.y = b2.y - (ACOEF * C2.y - NS2.y);
    r.z = b2.z - (ACOEF * C2.z - NS2.z);
    r.w = b2.w - (ACOEF * C2.w - NS2.w);
    g_P[0][o.i2] = r;
}

// One Arnoldi step (runtime j), single sweep, 2 points/thread:
//   p = ew*zin - sum_{k<j} e_k P[k]  (4 LDG.128 footprint per vector per thread)
//   P[j] = p (j>0); zout = A(p)
//   dots <P[k],z> (descending k, L1-warm), <p,z>, <p,p>
// Epilogue: Gram recurrence -> Hm column + next combo coeffs (validated R4 math)
__global__ void __launch_bounds__(TPB, 4) k_arn(int j) {
    const float4* __restrict__ zin;
    float4* __restrict__ zout;
    if (j == 0)      { zin = g_P[0]; zout = g_zA; }
    else if (j & 1)  { zin = g_zA;   zout = g_zB; }
    else             { zin = g_zB;   zout = g_zA; }

    __shared__ float es[RESTART];
    if (threadIdx.x < RESTART) es[threadIdx.x] = g_e[threadIdx.x];
    __syncthreads();
    float ew = (j == 0) ? 1.0f : g_ew;

    Geo o = mkgeo();
    int lane = threadIdx.x & 31, warp = threadIdx.x >> 5;

    // ---- pass 1: linear combination with 5-point footprints ----
    float4 pc1, pn1, pc2, pn2;
    {
        float4 C1, NS1, C2, NS2;
        loadF2(zin, o, lane, C1, NS1, C2, NS2);
        pc1.x = ew * C1.x;  pc1.y = ew * C1.y;  pc1.z = ew * C1.z;  pc1.w = ew * C1.w;
        pn1.x = ew * NS1.x; pn1.y = ew * NS1.y; pn1.z = ew * NS1.z; pn1.w = ew * NS1.w;
        pc2.x = ew * C2.x;  pc2.y = ew * C2.y;  pc2.z = ew * C2.z;  pc2.w = ew * C2.w;
        pn2.x = ew * NS2.x; pn2.y = ew * NS2.y; pn2.z = ew * NS2.z; pn2.w = ew * NS2.w;
    }
#pragma unroll 2
    for (int k = 0; k < j; k++) {
        float e = es[k];
        float4 C1, NS1, C2, NS2;
        loadF2(g_P[k], o, lane, C1, NS1, C2, NS2);
        pc1.x -= e * C1.x;  pc1.y -= e * C1.y;  pc1.z -= e * C1.z;  pc1.w -= e * C1.w;
        pn1.x -= e * NS1.x; pn1.y -= e * NS1.y; pn1.z -= e * NS1.z; pn1.w -= e * NS1.w;
        pc2.x -= e * C2.x;  pc2.y -= e * C2.y;  pc2.z -= e * C2.z;  pc2.w -= e * C2.w;
        pn2.x -= e * NS2.x; pn2.y -= e * NS2.y; pn2.z -= e * NS2.z; pn2.w -= e * NS2.w;
    }

    if (j > 0) { g_P[j][o.i1] = pc1; g_P[j][o.i2] = pc2; }

    float4 z1, z2;
    z1.x = ACOEF * pc1.x - pn1.x;
    z1.y = ACOEF * pc1.y - pn1.y;
    z1.z = ACOEF * pc1.z - pn1.z;
    z1.w = ACOEF * pc1.w - pn1.w;
    z2.x = ACOEF * pc2.x - pn2.x;
    z2.y = ACOEF * pc2.y - pn2.y;
    z2.z = ACOEF * pc2.z - pn2.z;
    z2.w = ACOEF * pc2.w - pn2.w;
    zout[o.i1] = z1;
    zout[o.i2] = z2;

    // ---- pass 2: dots (descending k: recent footprints are L1-warm) ----
    __shared__ float sred[NPART][TPB / 32];
#pragma unroll 4
    for (int k = j - 1; k >= 0; k--) {
        float d = warpSum(dot4(g_P[k][o.i1], z1) + dot4(g_P[k][o.i2], z2));
        if (lane == 0) sred[k][warp] = d;
    }
    {
        float dj = warpSum(dot4(pc1, z1) + dot4(pc2, z2));
        if (lane == 0) sred[j][warp] = dj;
        float nr = warpSum(dot4(pc1, pc1) + dot4(pc2, pc2));
        if (lane == 0) sred[j + 1][warp] = nr;
    }
    __syncthreads();
    int t = threadIdx.x;
    int nk = j + 2;
    if (t < nk) {
        float s = 0.f;
#pragma unroll
        for (int w = 0; w < TPB / 32; w++) s += sred[t][w];
        g_part[t][blockIdx.x] = s;
        __threadfence();
    }
    __syncthreads();

    if (isLastBlock()) {
        __shared__ float tot[NPART];
        for (int k = warp; k < nk; k += TPB / 32) {
            float s = 0.f;
            for (int b = lane; b < NBLK; b += 32) s += g_part[k][b];
            s = warpSum(s);
            if (lane == 0) tot[k] = s;
        }
        __syncthreads();

        __shared__ float s_sig[NV], s_h[NV];
        if (t == 0) {
            float hn = sqrtf(tot[j + 1]);
            g_sig[j] = 1.0f / (hn + EPSF);
            if (j > 0) g_Hm[j * RESTART + (j - 1)] = hn;
            else       g_beta = hn;
            g_Q[j * NV + j] = tot[j + 1];
        }
        __syncthreads();
        if (t <= j) s_sig[t] = g_sig[t];
        __syncthreads();
        // Q column j via recurrence: <P[t],P[j]> = ew*hp[t] - sum_m e_m Q[t][m]
        if (t < j) {
            float q = ew * g_hp[t];
            for (int m = 0; m < j; m++) q -= es[m] * g_Q[t * NV + m];
            g_Q[t * NV + j] = q;
            g_Q[j * NV + t] = q;
        }
        if (t <= j) {
            s_h[t]  = s_sig[t] * s_sig[j] * tot[t];   // true h_k
            g_hp[t] = tot[t];
        }
        __syncthreads();
        if (t <= j) {
            float gh = 0.f;
            for (int m = 0; m <= j; m++)
                gh += s_sig[t] * s_sig[m] * g_Q[t * NV + m] * s_h[m];
            float c = 2.0f * s_h[t] - gh;             // h + h2,  h2 = h - Gh
            g_Hm[t * RESTART + j] = c;
            g_e[t] = c * s_sig[t];
        }
        if (t == 0) { g_ew = s_sig[j]; g_cnt = 0; }
    }
}

// ||P[16]||^2 -> Hm[16][15]; then 16x16 normal-equations solve; y pre-scaled
__global__ void __launch_bounds__(TPB, 4) k_fin() {
    __shared__ float es[RESTART];
    if (threadIdx.x < RESTART) es[threadIdx.x] = g_e[threadIdx.x];
    __syncthreads();
    float ew = g_ew;

    Geo o = mkgeo();
    int lane = threadIdx.x & 31, warp = threadIdx.x >> 5;
    float4 za = g_zB[o.i1], zb = g_zB[o.i2];   // z' of step 15 (odd -> zB)
    float4 p1, p2;
    p1.x = ew * za.x; p1.y = ew * za.y; p1.z = ew * za.z; p1.w = ew * za.w;
    p2.x = ew * zb.x; p2.y = ew * zb.y; p2.z = ew * zb.z; p2.w = ew * zb.w;
#pragma unroll 4
    for (int k = 0; k < RESTART; k++) {
        float e = es[k];
        float4 v = g_P[k][o.i1];
        p1.x -= e * v.x; p1.y -= e * v.y; p1.z -= e * v.z; p1.w -= e * v.w;
        v = g_P[k][o.i2];
        p2.x -= e * v.x; p2.y -= e * v.y; p2.z -= e * v.z; p2.w -= e * v.w;
    }
    __shared__ float sred[TPB / 32];
    float nr = warpSum(dot4(p1, p1) + dot4(p2, p2));
    if (lane == 0) sred[warp] = nr;
    __syncthreads();
    if (threadIdx.x == 0) {
        float s = 0.f;
#pragma unroll
        for (int w = 0; w < TPB / 32; w++) s += sred[w];
        g_part[0][blockIdx.x] = s;
        __threadfence();
    }
    __syncthreads();

    if (isLastBlock()) {
        int t = threadIdx.x;
        __shared__ float tot[1];
        if (warp == 0) {
            float s = 0.f;
            for (int b = lane; b < NBLK; b += 32) s += g_part[0][b];
            s = warpSum(s);
            if (lane == 0) tot[0] = s;
        }
        __syncthreads();
        if (t == 0) g_Hm[16 * RESTART + 15] = sqrtf(tot[0]);
        __syncthreads();

        __shared__ float sG[RESTART][RESTART], sf[RESTART], rhs[RESTART];
        {
            int a = t >> 4, b2 = t & 15;     // 256 threads = 16x16
            float su = 0.f;
            for (int r = 0; r < NV; r++)
                su += g_Hm[r * RESTART + a] * g_Hm[r * RESTART + b2];
            sG[a][b2] = su + ((a == b2) ? EPSF : 0.f);
        }
        if (t < RESTART) rhs[t] = g_Hm[t] * g_beta;   // Hm row 0
        __syncthreads();

        for (int p = 0; p < RESTART; p++) {
            if (t > p && t < RESTART) sf[t] = sG[t][p] / sG[p][p];
            __syncthreads();
            int r = t >> 4, c = t & 15;
            if (r > p && c > p) sG[r][c] -= sf[r] * sG[p][c];
            if (t > p && t < RESTART) rhs[t] -= sf[t] * rhs[p];
            __syncthreads();
        }
        if (t == 0) {
            for (int p = RESTART - 1; p >= 0; p--) {
                float su = rhs[p];
                for (int c = p + 1; c < RESTART; c++) su -= sG[p][c] * rhs[c];
                rhs[p] = su / sG[p][p];
            }
        }
        __syncthreads();
        if (t < RESTART) g_y[t] = rhs[t] * g_sig[t];
        if (t == 0) g_cnt = 0;
    }
}

// x += sum_k y_k P[k]  (y pre-scaled by sigma); optionally emit
__global__ void __launch_bounds__(TPB, 4) k_xupd(float4* __restrict__ out) {
    __shared__ float ys[RESTART];
    if (threadIdx.x < RESTART) ys[threadIdx.x] = g_y[threadIdx.x];
    __syncthreads();
    Geo o = mkgeo();
    float4 s1 = g_x[o.i1], s2 = g_x[o.i2];
#pragma unroll 4
    for (int k = 0; k < RESTART; k++) {
        float y = ys[k];
        float4 v = g_P[k][o.i1];
        s1.x += y * v.x; s1.y += y * v.y; s1.z += y * v.z; s1.w += y * v.w;
        v = g_P[k][o.i2];
        s2.x += y * v.x; s2.y += y * v.y; s2.z += y * v.z; s2.w += y * v.w;
    }
    g_x[o.i1] = s1;
    g_x[o.i2] = s2;
    if (out) { out[o.i1] = s1; out[o.i2] = s2; }
}

// ---------------- host orchestration ----------------------------------------
extern "C" void kernel_launch(void* const* d_in, const int* in_sizes, int n_in,
                              void* d_out, int out_size) {
    (void)in_sizes; (void)n_in; (void)out_size;
    const float4* src   = (const float4*)d_in[0];
    const float4* guess = (const float4*)d_in[1];
    float4* out = (float4*)d_out;

    k_init<<<NBLK, TPB>>>(guess);

    for (int c = 0; c < NCYC; c++) {
        k_resid<<<NBLK, TPB>>>(src);
        for (int j = 0; j < RESTART; j++)
            k_arn<<<NBLK, TPB>>>(j);
        k_fin<<<NBLK, TPB>>>();
        k_xupd<<<NBLK, TPB>>>(c == NCYC - 1 ? out : nullptr);
    }
}